// round 1
// baseline (speedup 1.0000x reference)
#include <cuda_runtime.h>
#include <math.h>

// DehLoss: O(n^2) pairwise Gaussian-kernel loss, n = 8192.
//   R_i = g1_i + log(y_i), h = 1.3 * n^-0.2
//   dr_ij = (R_i - R_j)/h
//   Dk_j  = sum_i d_i * phi(dr_ij)            (phi = normal pdf)
//   LP_j  = sum_i L_i * ndtr(dr_ij),  L_i = exp(g2_i - g1_i)
//   out   = -(S1 + S2 + S3 + S4)
//
// ndtr via Abramowitz-Stegun 26.2.17 (reuses phi, abs err < 7.5e-8):
//   t = 1/(1 + p|x|), q = phi(x) * poly5(t)   -> upper-tail prob for |x|
//   ndtr(x) = 0.5 + copysign(0.5 - q, x)
// The 0.5*sum(L) constant is hoisted out of the O(n^2) loop into finalize.

#define N      8192
#define SPLITS 16
#define CHUNK  (N / SPLITS)   // 512
#define JT     128

__device__ float4 g_pack[N];              // {Rh = R/h, d, L, unused}
__device__ float  g_partDk[SPLITS * N];
__device__ float  g_partLP[SPLITS * N];

__device__ __forceinline__ float ex2f_(float x) {
    float r; asm("ex2.approx.ftz.f32 %0, %1;" : "=f"(r) : "f"(x)); return r;
}
__device__ __forceinline__ float rcpf_(float x) {
    float r; asm("rcp.approx.ftz.f32 %0, %1;" : "=f"(r) : "f"(x)); return r;
}

__global__ void setup_kernel(const float* __restrict__ mz,
                             const float* __restrict__ y,
                             const float* __restrict__ delta,
                             float inv_h) {
    int i = blockIdx.x * blockDim.x + threadIdx.x;
    if (i < N) {
        float g1 = mz[2 * i];
        float g2 = mz[2 * i + 1];
        float R  = g1 + logf(y[i]);
        float4 p;
        p.x = R * inv_h;            // pre-scaled by 1/h
        p.y = delta[i];
        p.z = expf(g2 - g1);        // L_i
        p.w = 0.0f;
        g_pack[i] = p;
    }
}

__global__ void __launch_bounds__(JT) pair_kernel() {
    __shared__ float4 sh[CHUNK];
    const int j    = blockIdx.x * JT + threadIdx.x;
    const int base = blockIdx.y * CHUNK;

    for (int k = threadIdx.x; k < CHUNK; k += JT)
        sh[k] = g_pack[base + k];
    const float Rhj = g_pack[j].x;
    __syncthreads();

    // constants: C1 = -0.5*log2(e), C2 = log2(1/sqrt(2*pi))
    const float C1 = -0.72134752044448170f;
    const float C2 = -1.32574806473615923f;
    const float PP =  0.2316419f;
    const float B5 =  1.330274429f, B4 = -1.821255978f, B3 = 1.781477937f;
    const float B2 = -0.356563782f, B1 =  0.319381530f;

    float dk = 0.0f, lp = 0.0f;
    #pragma unroll 8
    for (int k = 0; k < CHUNK; ++k) {
        float4 p  = sh[k];
        float dr  = p.x - Rhj;                      // (R_i - R_j)/h
        float s   = dr * dr;
        float phi = ex2f_(fmaf(s, C1, C2));         // pdf, 1/sqrt(2pi) folded in
        dk = fmaf(p.y, phi, dk);                    // Dk partial

        float den  = fmaf(fabsf(dr), PP, 1.0f);
        float t    = rcpf_(den);
        float poly = fmaf(t, B5, B4);
        poly = fmaf(t, poly, B3);
        poly = fmaf(t, poly, B2);
        poly = fmaf(t, poly, B1);
        poly = t * poly;
        float u = fmaf(-phi, poly, 0.5f);           // 0.5 - upper-tail(|dr|)
        float v = copysignf(u, dr);                 // ndtr(dr) - 0.5
        lp = fmaf(p.z, v, lp);                      // LP partial (0.5*L hoisted)
    }

    g_partDk[blockIdx.y * N + j] = dk;
    g_partLP[blockIdx.y * N + j] = lp;
}

__global__ void __launch_bounds__(1024) finalize_kernel(const float* __restrict__ mz,
                                                        const float* __restrict__ delta,
                                                        float h, float* __restrict__ out) {
    __shared__ double red[1024];
    const int tid = threadIdx.x;

    // global sum of L (for the hoisted 0.5*Lsum term)
    double ls = 0.0;
    for (int j = tid; j < N; j += 1024) ls += (double)g_pack[j].z;
    red[tid] = ls;
    __syncthreads();
    for (int s = 512; s > 0; s >>= 1) {
        if (tid < s) red[tid] += red[tid + s];
        __syncthreads();
    }
    const float Lsum = (float)red[0];
    __syncthreads();

    const float invn   = 1.0f / (float)N;
    const float inv_nh = 1.0f / ((float)N * h);

    double acc = 0.0;
    for (int j = tid; j < N; j += 1024) {
        float dkraw = 0.0f, lpraw = 0.0f;
        #pragma unroll
        for (int s2 = 0; s2 < SPLITS; ++s2) {
            dkraw += g_partDk[s2 * N + j];
            lpraw += g_partLP[s2 * N + j];
        }
        float Dk = dkraw * inv_nh;
        float LP = (lpraw + 0.5f * Lsum) * invn;
        float dj = delta[j];
        float g2 = mz[2 * j + 1];
        float R  = g_pack[j].x * h;
        // S1 + S2 + S3 + S4 per-j contribution (all carry 1/n, applied at end)
        acc += (double)(dj * (g2 - R + logf(Dk + 1e-15f) - logf(LP + 1e-15f)));
    }
    red[tid] = acc;
    __syncthreads();
    for (int s = 512; s > 0; s >>= 1) {
        if (tid < s) red[tid] += red[tid + s];
        __syncthreads();
    }
    if (tid == 0) out[0] = (float)(-red[0] / (double)N);
}

extern "C" void kernel_launch(void* const* d_in, const int* in_sizes, int n_in,
                              void* d_out, int out_size) {
    const float* mz    = (const float*)d_in[0];
    const float* y     = (const float*)d_in[1];
    const float* delta = (const float*)d_in[2];
    float* out = (float*)d_out;

    const double hd = 1.3 * pow((double)N, -0.2);

    setup_kernel<<<N / 256, 256>>>(mz, y, delta, (float)(1.0 / hd));
    dim3 grid(N / JT, SPLITS);
    pair_kernel<<<grid, JT>>>();
    finalize_kernel<<<1, 1024>>>(mz, delta, (float)hd, out);
}

// round 2
// speedup vs baseline: 1.0636x; 1.0636x over previous
#include <cuda_runtime.h>
#include <math.h>

// DehLoss: O(n^2) pairwise Gaussian-kernel loss, n = 8192.
// R_i = g1_i + log(y_i), h = 1.3*n^-0.2, dr_ij = (R_i - R_j)/h
// Dk_j = sum_i d_i*phi(dr_ij);  LP_j = sum_i L_i*ndtr(dr_ij), L_i = exp(g2_i-g1_i)
// out = -(S1+S2+S3+S4)
//
// R2 optimizations:
//  - f32x2 packed math (fma/add/mul.rn.f32x2): 2 columns per iter
//  - ndtr via AS 26.2.16 (3-term, abs err 1e-5), reusing the Gaussian pdf
//  - paired rcp: one MUFU rcp serves both lanes (1/(ab)*b, 1/(ab)*a)
//  - sign application via or.b64 (0.5 - q >= 0 always)
//  - rows compacted to d_j==1 (deterministic single-block scan): 30% fewer pairs
//  - 0.5*sum(L) hoisted out of the O(n^2) loop

#define N      8192
#define SPLITS 16
#define CHUNK  (N / SPLITS)   // 512 columns per split
#define JT     128

typedef unsigned long long u64;

__device__ float4 g_A[N / 2];     // {Rh_2m, Rh_2m+1, d_2m, d_2m+1}
__device__ float2 g_Lp[N / 2];    // {L_2m, L_2m+1}
__device__ float  g_rowRh[N];     // compacted Rh_j for rows with d_j=1
__device__ int    g_M;            // number of compacted rows
__device__ float  g_partDk[SPLITS * N];
__device__ float  g_partLP[SPLITS * N];

__device__ __forceinline__ float ex2f_(float x) {
    float r; asm("ex2.approx.ftz.f32 %0, %1;" : "=f"(r) : "f"(x)); return r;
}
__device__ __forceinline__ float rcpf_(float x) {
    float r; asm("rcp.approx.ftz.f32 %0, %1;" : "=f"(r) : "f"(x)); return r;
}
__device__ __forceinline__ u64 pk2(float lo, float hi) {
    u64 r; asm("mov.b64 %0, {%1, %2};" : "=l"(r) : "f"(lo), "f"(hi)); return r;
}
__device__ __forceinline__ void upk2(u64 v, float& lo, float& hi) {
    asm("mov.b64 {%0, %1}, %2;" : "=f"(lo), "=f"(hi) : "l"(v));
}
__device__ __forceinline__ u64 fma2_(u64 a, u64 b, u64 c) {
    u64 d; asm("fma.rn.f32x2 %0, %1, %2, %3;" : "=l"(d) : "l"(a), "l"(b), "l"(c)); return d;
}
__device__ __forceinline__ u64 mul2_(u64 a, u64 b) {
    u64 d; asm("mul.rn.f32x2 %0, %1, %2;" : "=l"(d) : "l"(a), "l"(b)); return d;
}
__device__ __forceinline__ u64 add2_(u64 a, u64 b) {
    u64 d; asm("add.rn.f32x2 %0, %1, %2;" : "=l"(d) : "l"(a), "l"(b)); return d;
}

__global__ void setup_kernel(const float* __restrict__ mz,
                             const float* __restrict__ y,
                             const float* __restrict__ delta,
                             float inv_h) {
    int m = blockIdx.x * blockDim.x + threadIdx.x;
    if (m < N / 2) {
        int i = 2 * m;
        float g1a = mz[2 * i],     g2a = mz[2 * i + 1];
        float g1b = mz[2 * i + 2], g2b = mz[2 * i + 3];
        float4 a;
        a.x = (g1a + logf(y[i]))     * inv_h;   // Rh = R/h
        a.y = (g1b + logf(y[i + 1])) * inv_h;
        a.z = delta[i];
        a.w = delta[i + 1];
        g_A[m] = a;
        g_Lp[m] = make_float2(expf(g2a - g1a), expf(g2b - g1b));
    }
}

// Deterministic single-block compaction of rows with d_j = 1.
__global__ void __launch_bounds__(1024) compact_kernel(const float* __restrict__ delta) {
    __shared__ int cnt[1024];
    const int t = threadIdx.x;
    const int base = t * 8;
    int flags[8]; int c = 0;
    #pragma unroll
    for (int q = 0; q < 8; ++q) { flags[q] = delta[base + q] > 0.5f; c += flags[q]; }
    cnt[t] = c;
    __syncthreads();
    for (int off = 1; off < 1024; off <<= 1) {
        int v = (t >= off) ? cnt[t - off] : 0;
        __syncthreads();
        cnt[t] += v;
        __syncthreads();
    }
    int pos = cnt[t] - c;   // exclusive prefix
    #pragma unroll
    for (int q = 0; q < 8; ++q) {
        if (flags[q]) {
            int j = base + q;
            float4 a = g_A[j >> 1];
            g_rowRh[pos] = (j & 1) ? a.y : a.x;
            pos++;
        }
    }
    if (t == 1023) g_M = cnt[1023];
}

__global__ void __launch_bounds__(JT) pair_kernel() {
    __shared__ float4 shA[CHUNK / 2];
    __shared__ float2 shL[CHUNK / 2];
    const int M = g_M;
    if ((int)(blockIdx.x * JT) >= M) return;

    const int c  = blockIdx.x * JT + threadIdx.x;
    const int cc = min(c, M - 1);
    const int base2 = blockIdx.y * (CHUNK / 2);

    for (int k = threadIdx.x; k < CHUNK / 2; k += JT) {
        shA[k] = g_A[base2 + k];
        shL[k] = g_Lp[base2 + k];
    }
    const float Rhj = g_rowRh[cc];
    __syncthreads();

    // C1 = -0.5*log2(e), C2 = log2(1/sqrt(2*pi)); AS 26.2.16: p=0.33267,
    // a1=0.4361836, a2=-0.1201676, a3=0.9372980 (negated for the 0.5 - q fma).
    const u64 nRhj2 = pk2(-Rhj, -Rhj);
    const u64 C1_2  = pk2(-0.72134752044448170f, -0.72134752044448170f);
    const u64 C2_2  = pk2(-1.32574806473615923f, -1.32574806473615923f);
    const u64 PP2   = pk2(0.33267f, 0.33267f);
    const u64 ONE2  = pk2(1.0f, 1.0f);
    const u64 HALF2 = pk2(0.5f, 0.5f);
    const u64 NA1_2 = pk2(-0.4361836f, -0.4361836f);
    const u64 NA2_2 = pk2( 0.1201676f,  0.1201676f);
    const u64 NA3_2 = pk2(-0.9372980f, -0.9372980f);
    const u64 AMSK  = 0x7FFFFFFF7FFFFFFFULL;
    const u64 SMSK  = 0x8000000080000000ULL;

    u64 dk2 = 0ULL, lp2 = 0ULL;   // packed {0.f, 0.f}

    #pragma unroll 8
    for (int k = 0; k < CHUNK / 2; ++k) {
        float4 a = shA[k];
        float2 L = shL[k];
        u64 Rh2 = pk2(a.x, a.y);
        u64 d2  = pk2(a.z, a.w);
        u64 L2  = pk2(L.x, L.y);

        u64 dr2 = add2_(Rh2, nRhj2);               // (R_i - R_j)/h, 2 lanes
        u64 t1  = mul2_(dr2, C1_2);
        u64 e2  = fma2_(t1, dr2, C2_2);            // -dr^2/2*log2e + log2(1/sqrt2pi)
        float elo, ehi; upk2(e2, elo, ehi);
        u64 phi2 = pk2(ex2f_(elo), ex2f_(ehi));    // normal pdf, both lanes
        dk2 = fma2_(d2, phi2, dk2);

        u64 adr2 = dr2 & AMSK;                     // |dr|
        u64 den2 = fma2_(adr2, PP2, ONE2);         // 1 + p|dr|
        float dlo, dhi; upk2(den2, dlo, dhi);
        float rr = rcpf_(dlo * dhi);               // one rcp for both lanes
        u64 t2 = pk2(rr * dhi, rr * dlo);          // {1/dlo, 1/dhi}

        u64 p2 = fma2_(t2, NA3_2, NA2_2);          // -poly3(t), Horner
        p2 = fma2_(t2, p2, NA1_2);
        p2 = mul2_(t2, p2);
        u64 u2 = fma2_(phi2, p2, HALF2);           // 0.5 - q >= 0
        u64 v2 = u2 | (dr2 & SMSK);                // ndtr(dr) - 0.5
        lp2 = fma2_(L2, v2, lp2);
    }

    float dka, dkb, lpa, lpb;
    upk2(dk2, dka, dkb);
    upk2(lp2, lpa, lpb);
    if (c < M) {
        g_partDk[blockIdx.y * N + c] = dka + dkb;
        g_partLP[blockIdx.y * N + c] = lpa + lpb;
    }
}

__global__ void __launch_bounds__(1024) finalize_kernel(const float* __restrict__ mz,
                                                        float h, float* __restrict__ out) {
    __shared__ double red[1024];
    const int t = threadIdx.x;
    const int M = g_M;

    // Sum of L over all i (hoisted 0.5*L term).
    double ls = 0.0;
    for (int m = t; m < N / 2; m += 1024) {
        float2 L = g_Lp[m];
        ls += (double)L.x + (double)L.y;
    }
    red[t] = ls;
    __syncthreads();
    for (int s = 512; s > 0; s >>= 1) { if (t < s) red[t] += red[t + s]; __syncthreads(); }
    const float Lsum = (float)red[0];
    __syncthreads();

    double acc = 0.0;
    // S1 + S2 contribution over all j: d_j*(g2_j - R_j)
    for (int j = t; j < N; j += 1024) {
        float4 a = g_A[j >> 1];
        float Rh = (j & 1) ? a.y : a.x;
        float d  = (j & 1) ? a.w : a.z;
        float g2 = mz[2 * j + 1];
        acc += (double)(d * (g2 - Rh * h));
    }
    // S3 + S4 over compacted rows (d_j = 1 by construction)
    const float inv_nh = 1.0f / ((float)N * h);
    const float invn   = 1.0f / (float)N;
    for (int c = t; c < M; c += 1024) {
        float dk = 0.0f, lp = 0.0f;
        #pragma unroll
        for (int s2 = 0; s2 < SPLITS; ++s2) {
            dk += g_partDk[s2 * N + c];
            lp += g_partLP[s2 * N + c];
        }
        float Dk = dk * inv_nh;
        float LP = (lp + 0.5f * Lsum) * invn;
        acc += (double)(logf(Dk + 1e-15f) - logf(LP + 1e-15f));
    }
    red[t] = acc;
    __syncthreads();
    for (int s = 512; s > 0; s >>= 1) { if (t < s) red[t] += red[t + s]; __syncthreads(); }
    if (t == 0) out[0] = (float)(-red[0] / (double)N);
}

extern "C" void kernel_launch(void* const* d_in, const int* in_sizes, int n_in,
                              void* d_out, int out_size) {
    const float* mz    = (const float*)d_in[0];
    const float* y     = (const float*)d_in[1];
    const float* delta = (const float*)d_in[2];
    float* out = (float*)d_out;

    const double hd = 1.3 * pow((double)N, -0.2);

    setup_kernel<<<(N / 2 + 255) / 256, 256>>>(mz, y, delta, (float)(1.0 / hd));
    compact_kernel<<<1, 1024>>>(delta);
    dim3 grid(N / JT, SPLITS);
    pair_kernel<<<grid, JT>>>();
    finalize_kernel<<<1, 1024>>>(mz, (float)hd, out);
}

// round 3
// speedup vs baseline: 1.2988x; 1.2211x over previous
#include <cuda_runtime.h>
#include <math.h>

// DehLoss: O(n^2) pairwise Gaussian-kernel loss, n = 8192.
// R_i = g1_i + log(y_i), h = 1.3*n^-0.2, dr_ij = (R_i - R_j)/h
// Dk_j = sum_i d_i*phi(dr_ij);  LP_j = sum_i L_i*ndtr(dr_ij), L_i = exp(g2_i-g1_i)
// out = -(S1+S2+S3+S4)
//
// R3: parallel epilogue (32 blocks, one column per thread) + fused prep.
// Pair kernel (f32x2 packed math, AS 26.2.16 ndtr reusing phi, paired rcp,
// row compaction to d_j==1, hoisted 0.5*sum(L)) unchanged from R2.

#define N      8192
#define SPLITS 16
#define CHUNK  (N / SPLITS)   // 512 columns per split
#define JT     128
#define RB     32             // reduce blocks

typedef unsigned long long u64;

__device__ float4 g_A[N / 2];     // {Rh_2m, Rh_2m+1, d_2m, d_2m+1}
__device__ float2 g_Lp[N / 2];    // {L_2m, L_2m+1}
__device__ float  g_rowRh[N];     // compacted Rh_j for rows with d_j=1
__device__ int    g_M;            // number of compacted rows
__device__ float  g_Lsum;         // sum of L over all i
__device__ float  g_partDk[SPLITS * N];
__device__ float  g_partLP[SPLITS * N];
__device__ double g_bsum[RB];

__device__ __forceinline__ float ex2f_(float x) {
    float r; asm("ex2.approx.ftz.f32 %0, %1;" : "=f"(r) : "f"(x)); return r;
}
__device__ __forceinline__ float rcpf_(float x) {
    float r; asm("rcp.approx.ftz.f32 %0, %1;" : "=f"(r) : "f"(x)); return r;
}
__device__ __forceinline__ u64 pk2(float lo, float hi) {
    u64 r; asm("mov.b64 %0, {%1, %2};" : "=l"(r) : "f"(lo), "f"(hi)); return r;
}
__device__ __forceinline__ void upk2(u64 v, float& lo, float& hi) {
    asm("mov.b64 {%0, %1}, %2;" : "=f"(lo), "=f"(hi) : "l"(v));
}
__device__ __forceinline__ u64 fma2_(u64 a, u64 b, u64 c) {
    u64 d; asm("fma.rn.f32x2 %0, %1, %2, %3;" : "=l"(d) : "l"(a), "l"(b), "l"(c)); return d;
}
__device__ __forceinline__ u64 mul2_(u64 a, u64 b) {
    u64 d; asm("mul.rn.f32x2 %0, %1, %2;" : "=l"(d) : "l"(a), "l"(b)); return d;
}
__device__ __forceinline__ u64 add2_(u64 a, u64 b) {
    u64 d; asm("add.rn.f32x2 %0, %1, %2;" : "=l"(d) : "l"(a), "l"(b)); return d;
}

// Fused: per-i preprocessing + Lsum + deterministic compaction of d_j==1 rows.
__global__ void __launch_bounds__(1024) prep_kernel(const float* __restrict__ mz,
                                                    const float* __restrict__ y,
                                                    const float* __restrict__ delta,
                                                    float inv_h) {
    __shared__ int    cnt[1024];
    __shared__ double lred[1024];
    const int t = threadIdx.x;
    const int base = t * 8;

    float Rh[8]; int flags[8]; int c = 0; double ls = 0.0;
    #pragma unroll
    for (int q = 0; q < 8; ++q) {
        int j = base + q;
        float g1 = mz[2 * j], g2 = mz[2 * j + 1];
        float R = g1 + logf(y[j]);
        Rh[q] = R * inv_h;
        float d = delta[j];
        float L = expf(g2 - g1);
        ls += (double)L;
        flags[q] = d > 0.5f;
        c += flags[q];
        if ((q & 1) == 1) {
            float4 a; a.x = Rh[q - 1]; a.y = Rh[q];
            a.z = (float)flags[q - 1]; a.w = (float)flags[q];
            g_A[j >> 1] = a;
        }
        if (q & 1) {
            float g2p = mz[2 * (j - 1) + 1], g1p = mz[2 * (j - 1)];
            g_Lp[j >> 1] = make_float2(expf(g2p - g1p), L);
        }
    }
    cnt[t] = c; lred[t] = ls;
    __syncthreads();
    for (int off = 1; off < 1024; off <<= 1) {
        int v = (t >= off) ? cnt[t - off] : 0;
        __syncthreads();
        cnt[t] += v;
        __syncthreads();
    }
    int pos = cnt[t] - c;
    #pragma unroll
    for (int q = 0; q < 8; ++q) {
        if (flags[q]) g_rowRh[pos++] = Rh[q];
    }
    if (t == 1023) g_M = cnt[1023];
    // Lsum reduction
    for (int s = 512; s > 0; s >>= 1) {
        if (t < s) lred[t] += lred[t + s];
        __syncthreads();
    }
    if (t == 0) g_Lsum = (float)lred[0];
}

__global__ void __launch_bounds__(JT) pair_kernel() {
    __shared__ float4 shA[CHUNK / 2];
    __shared__ float2 shL[CHUNK / 2];
    const int M = g_M;
    if ((int)(blockIdx.x * JT) >= M) return;

    const int c  = blockIdx.x * JT + threadIdx.x;
    const int cc = min(c, M - 1);
    const int base2 = blockIdx.y * (CHUNK / 2);

    for (int k = threadIdx.x; k < CHUNK / 2; k += JT) {
        shA[k] = g_A[base2 + k];
        shL[k] = g_Lp[base2 + k];
    }
    const float Rhj = g_rowRh[cc];
    __syncthreads();

    // C1 = -0.5*log2(e), C2 = log2(1/sqrt(2*pi)); AS 26.2.16: p=0.33267,
    // a1=0.4361836, a2=-0.1201676, a3=0.9372980 (negated for the 0.5 - q fma).
    const u64 nRhj2 = pk2(-Rhj, -Rhj);
    const u64 C1_2  = pk2(-0.72134752044448170f, -0.72134752044448170f);
    const u64 C2_2  = pk2(-1.32574806473615923f, -1.32574806473615923f);
    const u64 PP2   = pk2(0.33267f, 0.33267f);
    const u64 ONE2  = pk2(1.0f, 1.0f);
    const u64 HALF2 = pk2(0.5f, 0.5f);
    const u64 NA1_2 = pk2(-0.4361836f, -0.4361836f);
    const u64 NA2_2 = pk2( 0.1201676f,  0.1201676f);
    const u64 NA3_2 = pk2(-0.9372980f, -0.9372980f);
    const u64 AMSK  = 0x7FFFFFFF7FFFFFFFULL;
    const u64 SMSK  = 0x8000000080000000ULL;

    u64 dk2 = 0ULL, lp2 = 0ULL;

    #pragma unroll 8
    for (int k = 0; k < CHUNK / 2; ++k) {
        float4 a = shA[k];
        float2 L = shL[k];
        u64 Rh2 = pk2(a.x, a.y);
        u64 d2  = pk2(a.z, a.w);
        u64 L2  = pk2(L.x, L.y);

        u64 dr2 = add2_(Rh2, nRhj2);               // (R_i - R_j)/h, 2 lanes
        u64 t1  = mul2_(dr2, C1_2);
        u64 e2  = fma2_(t1, dr2, C2_2);
        float elo, ehi; upk2(e2, elo, ehi);
        u64 phi2 = pk2(ex2f_(elo), ex2f_(ehi));    // normal pdf, both lanes
        dk2 = fma2_(d2, phi2, dk2);

        u64 adr2 = dr2 & AMSK;                     // |dr|
        u64 den2 = fma2_(adr2, PP2, ONE2);         // 1 + p|dr|
        float dlo, dhi; upk2(den2, dlo, dhi);
        float rr = rcpf_(dlo * dhi);               // one rcp, both lanes
        u64 t2 = pk2(rr * dhi, rr * dlo);          // {1/dlo, 1/dhi}

        u64 p2 = fma2_(t2, NA3_2, NA2_2);          // -poly3(t), Horner
        p2 = fma2_(t2, p2, NA1_2);
        p2 = mul2_(t2, p2);
        u64 u2 = fma2_(phi2, p2, HALF2);           // 0.5 - q >= 0
        u64 v2 = u2 | (dr2 & SMSK);                // ndtr(dr) - 0.5
        lp2 = fma2_(L2, v2, lp2);
    }

    float dka, dkb, lpa, lpb;
    upk2(dk2, dka, dkb);
    upk2(lp2, lpa, lpb);
    if (c < M) {
        g_partDk[blockIdx.y * N + c] = dka + dkb;
        g_partLP[blockIdx.y * N + c] = lpa + lpb;
    }
}

// Parallel epilogue: one column (and one j of S1+S2) per thread, 32 blocks.
__global__ void __launch_bounds__(256) reduce_kernel(const float* __restrict__ mz,
                                                     float h) {
    __shared__ double red[256];
    const int t   = threadIdx.x;
    const int gid = blockIdx.x * 256 + t;    // 0 .. 8191
    const int M   = g_M;
    const float Lsum   = g_Lsum;
    const float inv_nh = 1.0f / ((float)N * h);
    const float invn   = 1.0f / (float)N;

    double acc = 0.0;

    // S1 + S2: d_j * (g2_j - R_j)
    {
        float4 a = g_A[gid >> 1];
        float Rh = (gid & 1) ? a.y : a.x;
        float d  = (gid & 1) ? a.w : a.z;
        float g2 = mz[2 * gid + 1];
        acc += (double)(d * (g2 - Rh * h));
    }
    // S3 + S4 over compacted rows
    if (gid < M) {
        float dk = 0.0f, lp = 0.0f;
        #pragma unroll
        for (int s2 = 0; s2 < SPLITS; ++s2) {
            dk += g_partDk[s2 * N + gid];
            lp += g_partLP[s2 * N + gid];
        }
        float Dk = dk * inv_nh;
        float LP = (lp + 0.5f * Lsum) * invn;
        acc += (double)(logf(Dk + 1e-15f) - logf(LP + 1e-15f));
    }
    red[t] = acc;
    __syncthreads();
    for (int s = 128; s > 0; s >>= 1) {
        if (t < s) red[t] += red[t + s];
        __syncthreads();
    }
    if (t == 0) g_bsum[blockIdx.x] = red[0];
}

__global__ void out_kernel(float* __restrict__ out) {
    double v = g_bsum[threadIdx.x];
    #pragma unroll
    for (int s = 16; s > 0; s >>= 1)
        v += __shfl_down_sync(0xFFFFFFFFu, v, s);
    if (threadIdx.x == 0) out[0] = (float)(-v / (double)N);
}

extern "C" void kernel_launch(void* const* d_in, const int* in_sizes, int n_in,
                              void* d_out, int out_size) {
    const float* mz    = (const float*)d_in[0];
    const float* y     = (const float*)d_in[1];
    const float* delta = (const float*)d_in[2];
    float* out = (float*)d_out;

    const double hd = 1.3 * pow((double)N, -0.2);

    prep_kernel<<<1, 1024>>>(mz, y, delta, (float)(1.0 / hd));
    dim3 grid(N / JT, SPLITS);
    pair_kernel<<<grid, JT>>>();
    reduce_kernel<<<RB, 256>>>(mz, (float)hd);
    out_kernel<<<1, 32>>>(out);
}